// round 1
// baseline (speedup 1.0000x reference)
#include <cuda_runtime.h>

#define EPSF 1e-8f
#define NC 128
#define NF 49

__global__ __launch_bounds__(NC, 1)
void causality_kernel(const float* __restrict__ x, float* __restrict__ out) {
    const int b   = blockIdx.x;
    const int tid = threadIdx.x;          // 128 threads, one channel each

    __shared__ float sx[NC * NF];         // staged input tile (25088 B)
    __shared__ float sS[NC];              // normalized channel sums
    __shared__ float sQ[NC];              // normalized channel sum-of-squares
    __shared__ float sLinv[NC];           // 1 / lehmer_denominator[n]
    __shared__ float red[NC];             // max reduction scratch

    const float* xb = x + (size_t)b * NC * NF;

    // Coalesced staging of this batch's tile into shared.
    #pragma unroll
    for (int i = tid; i < NC * NF; i += NC) sx[i] = xb[i];
    __syncthreads();

    // Per-channel raw sums + local max. smem row stride 49 -> bank index
    // advances by 17 per thread (gcd(17,32)=1): conflict-free.
    float s = 0.f, q = 0.f, mx = -1e30f;
    const float* row = sx + tid * NF;
    #pragma unroll
    for (int i = 0; i < NF; i++) {
        float v = row[i];
        s += v;
        q = fmaf(v, v, q);
        mx = fmaxf(mx, v);
    }

    // Block max reduction over 128 channel maxima.
    red[tid] = mx;
    __syncthreads();
    #pragma unroll
    for (int off = 64; off >= 1; off >>= 1) {
        if (tid < off) red[tid] = fmaxf(red[tid], red[tid + off]);
        __syncthreads();
    }
    const float M = red[0] + EPSF;

    // Normalization commutes with the channel sums.
    const float Sn = s / M;
    const float Qn = q / (M * M);
    sS[tid] = Sn;
    sQ[tid] = Qn;

    // lehmer_denominator[n] = (Q + 2eS + e^2 F + e) / (S + eF + e) + e
    {
        const float numd = Qn + 2.f * EPSF * Sn + EPSF * EPSF * (float)NF + EPSF;
        const float dend = Sn + EPSF * (float)NF + EPSF;
        sLinv[tid] = 1.f / (numd / dend + EPSF);
    }
    __syncthreads();

    // out[b,m,n] = ((Q[m]Q[n] + 2e S[m]S[n] + e^2 F^2 + e) /
    //              (S[m]S[n] + e F^2 + e) + e) * (1 / L[n])
    const float eF2  = EPSF * (float)(NF * NF);   // e * F^2
    const float e2F2 = EPSF * eF2;                 // e^2 * F^2
    float* ob = out + (size_t)b * NC * NC;

    #pragma unroll 4
    for (int idx = tid; idx < NC * NC; idx += NC) {
        const int m = idx >> 7;
        const int n = idx & (NC - 1);
        const float ss  = sS[m] * sS[n];
        const float num = fmaf(sQ[m], sQ[n], fmaf(2.f * EPSF, ss, e2F2 + EPSF));
        const float den = ss + eF2 + EPSF;
        ob[idx] = (num / den + EPSF) * sLinv[n];
    }
}

extern "C" void kernel_launch(void* const* d_in, const int* in_sizes, int n_in,
                              void* d_out, int out_size) {
    const float* x  = (const float*)d_in[0];
    float* out      = (float*)d_out;
    causality_kernel<<<2, NC>>>(x, out);
}